// round 4
// baseline (speedup 1.0000x reference)
#include <cuda_runtime.h>
#include <cstdint>
#include <math.h>

// ---------------------------------------------------------------------------
// ExpertRouter: h = silu(x@W1+b1); logits = h@W2+b2; top-2 softmax + aux loss.
// B=16384, D=4096, HID=2048, E=64.
// GEMM1: mma.sync m16n8k8 tf32, tf32x3 decomposition (fast, ~2e-5 logit noise).
// Near-tie rows (gap < TAU) recomputed exactly in fp32 by fixup kernels.
// Output layout (f32): [weights B*2 | top_idx(as float) B*2 | aux].
// ---------------------------------------------------------------------------

#define Bdim 16384
#define Ddim 4096
#define HIDd 2048
#define Ed   64
#define TAU  5e-4f
#define FIXCAP 4096

__device__ float g_H[(size_t)Bdim * HIDd];        // 134 MB intermediate
__device__ float g_W1t[(size_t)HIDd * Ddim];      // 33 MB transposed W1
__device__ float g_pprob[512 * Ed];
__device__ int   g_top1[Bdim];
__device__ int   g_fixcount;
__device__ int   g_fixlist[FIXCAP];

// ---- helpers ----
__device__ __forceinline__ float silu_f(float v) { return v / (1.0f + expf(-v)); }

__device__ __forceinline__ void split_tf32(float v, float& hi, float& lo) {
    uint32_t h;
    asm("cvt.rna.tf32.f32 %0, %1;" : "=r"(h) : "f"(v));
    hi = __uint_as_float(h);
    float r = v - hi;
    uint32_t l;
    asm("cvt.rna.tf32.f32 %0, %1;" : "=r"(l) : "f"(r));
    lo = __uint_as_float(l);
}

__device__ __forceinline__ void mma_tf32(float c[4],
                                         uint32_t a0, uint32_t a1, uint32_t a2, uint32_t a3,
                                         uint32_t b0, uint32_t b1) {
    asm("mma.sync.aligned.m16n8k8.row.col.f32.tf32.tf32.f32 "
        "{%0,%1,%2,%3}, {%4,%5,%6,%7}, {%8,%9}, {%0,%1,%2,%3};"
        : "+f"(c[0]), "+f"(c[1]), "+f"(c[2]), "+f"(c[3])
        : "r"(a0), "r"(a1), "r"(a2), "r"(a3), "r"(b0), "r"(b1));
}

// ---- packed f32x2 (router) ----
__device__ __forceinline__ unsigned long long pack2(float lo, float hi) {
    unsigned long long r;
    asm("mov.b64 %0, {%1, %2};" : "=l"(r) : "f"(lo), "f"(hi));
    return r;
}
__device__ __forceinline__ unsigned long long fma2(unsigned long long a,
                                                   unsigned long long b,
                                                   unsigned long long c) {
    unsigned long long d;
    asm("fma.rn.f32x2 %0, %1, %2, %3;" : "=l"(d) : "l"(a), "l"(b), "l"(c));
    return d;
}
__device__ __forceinline__ float2 unpack2(unsigned long long v) {
    float2 f;
    asm("mov.b64 {%0, %1}, %2;" : "=f"(f.x), "=f"(f.y) : "l"(v));
    return f;
}

// ---------------------------------------------------------------------------
__global__ void reset_kernel() { if (threadIdx.x == 0) g_fixcount = 0; }

// ---------------------------------------------------------------------------
// Prepass: W1t[n][k] = W1[k][n]
// ---------------------------------------------------------------------------
__global__ __launch_bounds__(256)
void transpose_W1(const float* __restrict__ W1) {
    __shared__ float s[32][33];
    const int n0 = blockIdx.x * 32;
    const int k0 = blockIdx.y * 32;
    const int tx = threadIdx.x & 31;
    const int ty = (threadIdx.x >> 5) * 4;
#pragma unroll
    for (int i = 0; i < 4; i++)
        s[ty + i][tx] = W1[(size_t)(k0 + ty + i) * HIDd + n0 + tx];
    __syncthreads();
#pragma unroll
    for (int i = 0; i < 4; i++)
        g_W1t[(size_t)(n0 + ty + i) * Ddim + k0 + tx] = s[tx][ty + i];
}

// ---------------------------------------------------------------------------
// GEMM1: H = silu(x @ W1 + b1), tf32x3 mma.sync.  (identical to R3 — validated)
// CTA 128x128, BK=32, 256 thr, warps 4(m) x 2(n), warp tile 32m x 64n.
// ---------------------------------------------------------------------------
#define LDA 36
#define PLANE (128 * LDA)
#define SMEM_FLOATS (8 * PLANE)

__global__ __launch_bounds__(256, 1)
void gemm1_tc(const float* __restrict__ x,
              const float* __restrict__ b1) {
    extern __shared__ float sm[];

    const int tid  = threadIdx.x;
    const int wid  = tid >> 5;
    const int lane = tid & 31;
    const int g = lane >> 2;
    const int t = lane & 3;
    const int rowBase = blockIdx.y * 128;
    const int colBase = blockIdx.x * 128;

    const int wm = (wid & 3) * 32;
    const int wn = (wid >> 2) * 64;

    float* sA[2][2];
    float* sB[2][2];
#pragma unroll
    for (int s = 0; s < 2; s++)
#pragma unroll
        for (int p = 0; p < 2; p++) {
            sA[s][p] = sm + (s * 2 + p) * PLANE;
            sB[s][p] = sm + 4 * PLANE + (s * 2 + p) * PLANE;
        }

    const float* xg = x + (size_t)rowBase * Ddim;
    const float* bg = g_W1t + (size_t)colBase * Ddim;

    const int ldRow0 = tid >> 3;
    const int ldCol  = (tid & 7) * 4;

    float acc[2][8][4];
#pragma unroll
    for (int mt = 0; mt < 2; mt++)
#pragma unroll
        for (int nt = 0; nt < 8; nt++)
#pragma unroll
            for (int r = 0; r < 4; r++) acc[mt][nt][r] = 0.0f;

    float4 av[4], bv[4];

#pragma unroll
    for (int i = 0; i < 4; i++) {
        int r = ldRow0 + 32 * i;
        av[i] = *(const float4*)(xg + (size_t)r * Ddim + ldCol);
        bv[i] = *(const float4*)(bg + (size_t)r * Ddim + ldCol);
    }
#pragma unroll
    for (int i = 0; i < 4; i++) {
        int r = ldRow0 + 32 * i;
        float4 hi, lo;
        split_tf32(av[i].x, hi.x, lo.x); split_tf32(av[i].y, hi.y, lo.y);
        split_tf32(av[i].z, hi.z, lo.z); split_tf32(av[i].w, hi.w, lo.w);
        *(float4*)(sA[0][0] + r * LDA + ldCol) = hi;
        *(float4*)(sA[0][1] + r * LDA + ldCol) = lo;
        split_tf32(bv[i].x, hi.x, lo.x); split_tf32(bv[i].y, hi.y, lo.y);
        split_tf32(bv[i].z, hi.z, lo.z); split_tf32(bv[i].w, hi.w, lo.w);
        *(float4*)(sB[0][0] + r * LDA + ldCol) = hi;
        *(float4*)(sB[0][1] + r * LDA + ldCol) = lo;
    }
    __syncthreads();

    const int NCHUNK = Ddim / 32;
    for (int kc = 0; kc < NCHUNK; kc++) {
        const int s = kc & 1;

        if (kc + 1 < NCHUNK) {
            const int k0 = (kc + 1) * 32;
#pragma unroll
            for (int i = 0; i < 4; i++) {
                int r = ldRow0 + 32 * i;
                av[i] = *(const float4*)(xg + (size_t)r * Ddim + k0 + ldCol);
                bv[i] = *(const float4*)(bg + (size_t)r * Ddim + k0 + ldCol);
            }
        }

        const uint32_t* Ah = (const uint32_t*)sA[s][0];
        const uint32_t* Al = (const uint32_t*)sA[s][1];
        const uint32_t* Bh = (const uint32_t*)sB[s][0];
        const uint32_t* Bl = (const uint32_t*)sB[s][1];
#pragma unroll
        for (int st = 0; st < 4; st++) {
            const int kk = st * 8;
            uint32_t ah[2][4], al[2][4];
#pragma unroll
            for (int mt = 0; mt < 2; mt++) {
                int base = (wm + mt * 16 + g) * LDA + kk + t;
                ah[mt][0] = Ah[base];            al[mt][0] = Al[base];
                ah[mt][1] = Ah[base + 8 * LDA];  al[mt][1] = Al[base + 8 * LDA];
                ah[mt][2] = Ah[base + 4];        al[mt][2] = Al[base + 4];
                ah[mt][3] = Ah[base + 8 * LDA + 4]; al[mt][3] = Al[base + 8 * LDA + 4];
            }
#pragma unroll
            for (int nt = 0; nt < 8; nt++) {
                int nbase = (wn + nt * 8 + g) * LDA + kk + t;
                uint32_t bh0 = Bh[nbase], bh1 = Bh[nbase + 4];
                uint32_t bl0 = Bl[nbase], bl1 = Bl[nbase + 4];
#pragma unroll
                for (int mt = 0; mt < 2; mt++) {
                    mma_tf32(acc[mt][nt], ah[mt][0], ah[mt][1], ah[mt][2], ah[mt][3], bh0, bh1);
                    mma_tf32(acc[mt][nt], ah[mt][0], ah[mt][1], ah[mt][2], ah[mt][3], bl0, bl1);
                    mma_tf32(acc[mt][nt], al[mt][0], al[mt][1], al[mt][2], al[mt][3], bh0, bh1);
                }
            }
        }

        if (kc + 1 < NCHUNK) {
            const int ns = (kc + 1) & 1;
#pragma unroll
            for (int i = 0; i < 4; i++) {
                int r = ldRow0 + 32 * i;
                float4 hi, lo;
                split_tf32(av[i].x, hi.x, lo.x); split_tf32(av[i].y, hi.y, lo.y);
                split_tf32(av[i].z, hi.z, lo.z); split_tf32(av[i].w, hi.w, lo.w);
                *(float4*)(sA[ns][0] + r * LDA + ldCol) = hi;
                *(float4*)(sA[ns][1] + r * LDA + ldCol) = lo;
                split_tf32(bv[i].x, hi.x, lo.x); split_tf32(bv[i].y, hi.y, lo.y);
                split_tf32(bv[i].z, hi.z, lo.z); split_tf32(bv[i].w, hi.w, lo.w);
                *(float4*)(sB[ns][0] + r * LDA + ldCol) = hi;
                *(float4*)(sB[ns][1] + r * LDA + ldCol) = lo;
            }
        }
        __syncthreads();
    }

#pragma unroll
    for (int nt = 0; nt < 8; nt++) {
        const int n0 = colBase + wn + nt * 8 + 2 * t;
        const float bs0 = b1[n0];
        const float bs1 = b1[n0 + 1];
#pragma unroll
        for (int mt = 0; mt < 2; mt++) {
            const int m0 = rowBase + wm + mt * 16 + g;
            float2 o0, o1;
            o0.x = silu_f(acc[mt][nt][0] + bs0);
            o0.y = silu_f(acc[mt][nt][1] + bs1);
            o1.x = silu_f(acc[mt][nt][2] + bs0);
            o1.y = silu_f(acc[mt][nt][3] + bs1);
            *(float2*)(g_H + (size_t)m0 * HIDd + n0)       = o0;
            *(float2*)(g_H + (size_t)(m0 + 8) * HIDd + n0) = o1;
        }
    }
}

// ---------------------------------------------------------------------------
// Router: logits = H @ W2 + b2; top-2 / softmax / prob partials / tie flags.
// ---------------------------------------------------------------------------
__global__ __launch_bounds__(256)
void router_kernel(const float* __restrict__ W2,
                   const float* __restrict__ b2,
                   float* __restrict__ outW,
                   float* __restrict__ outI) {
    __shared__ float sW2[128][Ed];
    __shared__ float sH[32][128];
    __shared__ float sProb[32][Ed];

    const int tid  = threadIdx.x;
    const int warp = tid >> 5;
    const int lane = tid & 31;
    const int rowBase = blockIdx.x * 32;

    unsigned long long acc[4] = {0ULL, 0ULL, 0ULL, 0ULL};

    for (int kc = 0; kc < HIDd; kc += 128) {
        __syncthreads();
#pragma unroll
        for (int i = 0; i < 8; i++) {
            int idx = tid + 256 * i;
            int r = idx >> 4, c4 = (idx & 15) * 4;
            *(float4*)&sW2[r][c4] = *(const float4*)&W2[(size_t)(kc + r) * Ed + c4];
        }
#pragma unroll
        for (int i = 0; i < 4; i++) {
            int idx = tid + 256 * i;
            int r = idx >> 5, c = (idx & 31) * 4;
            *(float4*)&sH[r][c] = *(const float4*)&g_H[(size_t)(rowBase + r) * HIDd + kc + c];
        }
        __syncthreads();

#pragma unroll 2
        for (int k4 = 0; k4 < 32; k4++) {
            unsigned long long wv0 = *(const unsigned long long*)&sW2[k4 * 4 + 0][lane * 2];
            unsigned long long wv1 = *(const unsigned long long*)&sW2[k4 * 4 + 1][lane * 2];
            unsigned long long wv2 = *(const unsigned long long*)&sW2[k4 * 4 + 2][lane * 2];
            unsigned long long wv3 = *(const unsigned long long*)&sW2[k4 * 4 + 3][lane * 2];
#pragma unroll
            for (int r = 0; r < 4; r++) {
                float4 h4 = *(const float4*)&sH[warp * 4 + r][k4 * 4];
                acc[r] = fma2(pack2(h4.x, h4.x), wv0, acc[r]);
                acc[r] = fma2(pack2(h4.y, h4.y), wv1, acc[r]);
                acc[r] = fma2(pack2(h4.z, h4.z), wv2, acc[r]);
                acc[r] = fma2(pack2(h4.w, h4.w), wv3, acc[r]);
            }
        }
    }

    const float b2a = b2[lane * 2];
    const float b2b = b2[lane * 2 + 1];

#pragma unroll
    for (int r = 0; r < 4; r++) {
        const int lrow = warp * 4 + r;
        float2 av = unpack2(acc[r]);
        float l0 = av.x + b2a;
        float l1 = av.y + b2b;
        const int id0 = lane * 2, id1 = lane * 2 + 1;

        float bvv, sv; int bi, si;
        if (l0 >= l1) { bvv = l0; bi = id0; sv = l1; si = id1; }
        else          { bvv = l1; bi = id1; sv = l0; si = id0; }

        float v1 = bvv; int i1 = bi;
#pragma unroll
        for (int off = 16; off; off >>= 1) {
            float ov = __shfl_down_sync(0xffffffffu, v1, off);
            int   oi = __shfl_down_sync(0xffffffffu, i1, off);
            if (ov > v1 || (ov == v1 && oi < i1)) { v1 = ov; i1 = oi; }
        }
        v1 = __shfl_sync(0xffffffffu, v1, 0);
        i1 = __shfl_sync(0xffffffffu, i1, 0);

        float cv; int ci;
        if (bi == i1) { cv = sv; ci = si; } else { cv = bvv; ci = bi; }
        float v2 = cv; int i2 = ci;
#pragma unroll
        for (int off = 16; off; off >>= 1) {
            float ov = __shfl_down_sync(0xffffffffu, v2, off);
            int   oi = __shfl_down_sync(0xffffffffu, i2, off);
            if (ov > v2 || (ov == v2 && oi < i2)) { v2 = ov; i2 = oi; }
        }
        v2 = __shfl_sync(0xffffffffu, v2, 0);
        i2 = __shfl_sync(0xffffffffu, i2, 0);

        // third-best value (for tie flagging)
        float v3 = -1e30f;
        if (id0 != i1 && id0 != i2) v3 = l0;
        if (id1 != i1 && id1 != i2 && l1 > v3) v3 = l1;
#pragma unroll
        for (int off = 16; off; off >>= 1) {
            float ov = __shfl_down_sync(0xffffffffu, v3, off);
            if (ov > v3) v3 = ov;
        }

        float p0 = expf(l0 - v1);
        float p1 = expf(l1 - v1);
        float ssum = p0 + p1;
#pragma unroll
        for (int off = 16; off; off >>= 1) ssum += __shfl_down_sync(0xffffffffu, ssum, off);
        ssum = __shfl_sync(0xffffffffu, ssum, 0);
        float inv = 1.0f / ssum;
        sProb[lrow][lane * 2]     = p0 * inv;
        sProb[lrow][lane * 2 + 1] = p1 * inv;

        if (lane == 0) {
            float d = expf(v2 - v1);
            float w0 = 1.0f / (1.0f + d);
            float w1 = d / (1.0f + d);
            size_t gb = (size_t)(rowBase + lrow);
            outW[gb * 2]     = w0;
            outW[gb * 2 + 1] = w1;
            outI[gb * 2]     = (float)i1;
            outI[gb * 2 + 1] = (float)i2;
            g_top1[gb]       = i1;
            if ((v1 - v2) < TAU || (v2 - v3) < TAU) {
                int pos = atomicAdd(&g_fixcount, 1);
                if (pos < FIXCAP) g_fixlist[pos] = (int)gb;
            }
        }
    }
    __syncthreads();

    if (tid < Ed) {
        float ps = 0.0f;
#pragma unroll
        for (int r = 0; r < 32; r++) ps += sProb[r][tid];
        g_pprob[(size_t)blockIdx.x * Ed + tid] = ps;
    }
}

// ---------------------------------------------------------------------------
// Fixup stage 1: recompute h (plain fp32, sequential k) for flagged rows.
// grid = (512 row-groups of 8, 8 col-slices of 256); empty groups exit.
// ---------------------------------------------------------------------------
__global__ __launch_bounds__(256)
void fixup_h(const float* __restrict__ x,
             const float* __restrict__ W1,
             const float* __restrict__ b1) {
    extern __shared__ float sX[];   // 8 * 2048 floats = 64 KB (half of k at a time)
    int cnt = g_fixcount; if (cnt > FIXCAP) cnt = FIXCAP;
    const int grp = blockIdx.x;
    if (grp * 8 >= cnt) return;
    int nr = cnt - grp * 8; if (nr > 8) nr = 8;
    const int tid = threadIdx.x;
    const int col = blockIdx.y * 256 + tid;

    int rows[8];
#pragma unroll
    for (int r = 0; r < 8; r++)
        rows[r] = g_fixlist[grp * 8 + (r < nr ? r : 0)];

    float acc[8];
#pragma unroll
    for (int r = 0; r < 8; r++) acc[r] = 0.0f;

    for (int half = 0; half < 2; half++) {
        __syncthreads();
        for (int idx = tid; idx < 8 * 2048; idx += 256) {
            int r = idx >> 11, kk = idx & 2047;
            sX[r * 2048 + kk] = x[(size_t)rows[r] * Ddim + half * 2048 + kk];
        }
        __syncthreads();
        for (int kk = 0; kk < 2048; kk += 4) {
            float4 xv[8];
#pragma unroll
            for (int r = 0; r < 8; r++)
                xv[r] = *(const float4*)&sX[r * 2048 + kk];
#pragma unroll
            for (int j = 0; j < 4; j++) {
                float w = W1[(size_t)(half * 2048 + kk + j) * HIDd + col];
#pragma unroll
                for (int r = 0; r < 8; r++)
                    acc[r] = fmaf(((const float*)&xv[r])[j], w, acc[r]);
            }
        }
    }
    const float bb = b1[col];
#pragma unroll
    for (int r = 0; r < 8; r++)
        if (r < nr)
            g_H[(size_t)rows[r] * HIDd + col] = silu_f(acc[r] + bb);
}

// ---------------------------------------------------------------------------
// Fixup stage 2: recompute logits + top2 + weights for flagged rows.
// grid = FIXCAP blocks, early exit.
// ---------------------------------------------------------------------------
__global__ __launch_bounds__(256)
void fixup_logits(const float* __restrict__ W2,
                  const float* __restrict__ b2,
                  float* __restrict__ outW,
                  float* __restrict__ outI) {
    int cnt = g_fixcount; if (cnt > FIXCAP) cnt = FIXCAP;
    const int fi = blockIdx.x;
    if (fi >= cnt) return;
    const int row = g_fixlist[fi];
    const int tid = threadIdx.x;
    const int e = tid & 63, q = tid >> 6;
    __shared__ float part[4][Ed];
    __shared__ float sLog[Ed];

    float a = 0.0f;
    const float* hrow = g_H + (size_t)row * HIDd;
    for (int k = q * 512; k < (q + 1) * 512; k++)
        a = fmaf(hrow[k], W2[(size_t)k * Ed + e], a);
    part[q][e] = a;
    __syncthreads();
    if (tid < Ed)
        sLog[tid] = part[0][tid] + part[1][tid] + part[2][tid] + part[3][tid] + b2[tid];
    __syncthreads();
    if (tid == 0) {
        float v1 = -1e30f, v2 = -1e30f; int i1 = 0, i2 = 0;
        for (int j = 0; j < Ed; j++) {
            float v = sLog[j];
            if (v > v1)      { v2 = v1; i2 = i1; v1 = v; i1 = j; }
            else if (v > v2) { v2 = v;  i2 = j; }
        }
        float d = expf(v2 - v1);
        outW[(size_t)row * 2]     = 1.0f / (1.0f + d);
        outW[(size_t)row * 2 + 1] = d / (1.0f + d);
        outI[(size_t)row * 2]     = (float)i1;
        outI[(size_t)row * 2 + 1] = (float)i2;
        g_top1[row] = i1;
    }
}

// ---------------------------------------------------------------------------
// Final: freq from g_top1, aux = E * sum freq_e * avgprob_e.
// ---------------------------------------------------------------------------
__global__ __launch_bounds__(256)
void aux_final(float* __restrict__ outAux) {
    __shared__ int   hist[Ed];
    __shared__ float term[Ed];
    const int tid = threadIdx.x;
    if (tid < Ed) hist[tid] = 0;
    __syncthreads();
    for (int r = tid; r < Bdim; r += 256)
        atomicAdd(&hist[g_top1[r]], 1);
    __syncthreads();
    if (tid < Ed) {
        float p = 0.0f;
        for (int b = 0; b < 512; b++) p += g_pprob[b * Ed + tid];
        term[tid] = ((float)hist[tid] * (1.0f / (float)Bdim)) *
                    (p * (1.0f / (float)Bdim));
    }
    __syncthreads();
    if (tid == 0) {
        float s = 0.0f;
        for (int e = 0; e < Ed; e++) s += term[e];
        outAux[0] = (float)Ed * s;
    }
}

// ---------------------------------------------------------------------------
extern "C" void kernel_launch(void* const* d_in, const int* in_sizes, int n_in,
                              void* d_out, int out_size) {
    const float* x  = (const float*)d_in[0];
    const float* W1 = (const float*)d_in[1];
    const float* b1 = (const float*)d_in[2];
    const float* W2 = (const float*)d_in[3];
    const float* b2 = (const float*)d_in[4];
    float* out = (float*)d_out;

    float* outW   = out;
    float* outI   = out + 2 * Bdim;
    float* outAux = out + 4 * Bdim;

    cudaFuncSetAttribute(gemm1_tc, cudaFuncAttributeMaxDynamicSharedMemorySize,
                         SMEM_FLOATS * (int)sizeof(float));
    cudaFuncSetAttribute(fixup_h, cudaFuncAttributeMaxDynamicSharedMemorySize,
                         8 * 2048 * (int)sizeof(float));

    reset_kernel<<<1, 32>>>();
    transpose_W1<<<dim3(HIDd / 32, Ddim / 32), 256>>>(W1);
    gemm1_tc<<<dim3(HIDd / 128, Bdim / 128), 256, SMEM_FLOATS * sizeof(float)>>>(x, b1);
    router_kernel<<<Bdim / 32, 256>>>(W2, b2, outW, outI);
    fixup_h<<<dim3(512, 8), 256, 8 * 2048 * sizeof(float)>>>(x, W1, b1);
    fixup_logits<<<FIXCAP, 256>>>(W2, b2, outW, outI);
    aux_final<<<1, 256>>>(outAux);
}

// round 5
// speedup vs baseline: 1.8477x; 1.8477x over previous
#include <cuda_runtime.h>
#include <cuda_fp16.h>
#include <cstdint>
#include <math.h>

// ---------------------------------------------------------------------------
// ExpertRouter: h = silu(x@W1+b1); logits = h@W2+b2; top-2 softmax + aux loss.
// B=16384, D=4096, HID=2048, E=64.
// GEMM1: plain fp16 mma.sync m16n8k16 (sigma_gap ~7e-4); rows with top-2/3
// gap < TAU recomputed exactly in fp32 by fixup kernels (indices exact).
// Output layout (f32): [weights B*2 | top_idx(as float) B*2 | aux].
// ---------------------------------------------------------------------------

#define Bdim 16384
#define Ddim 4096
#define HIDd 2048
#define Ed   64
#define TAU  1e-2f
#define FIXCAP 8192

__device__ float  g_H[(size_t)Bdim * HIDd];     // 134 MB intermediate h (fp32)
__device__ __half g_xh[(size_t)Bdim * Ddim];    // 134 MB x in fp16
__device__ __half g_W1h[(size_t)HIDd * Ddim];   // 16.8 MB W1^T in fp16
__device__ float  g_pprob[512 * Ed];
__device__ int    g_top1[Bdim];
__device__ int    g_fixcount;
__device__ int    g_fixlist[FIXCAP];

// ---- helpers ----
__device__ __forceinline__ float silu_f(float v) { return v / (1.0f + expf(-v)); }

__device__ __forceinline__ void mma_fp16(float c[4], const uint32_t a[4],
                                         uint32_t b0, uint32_t b1) {
    asm("mma.sync.aligned.m16n8k16.row.col.f32.f16.f16.f32 "
        "{%0,%1,%2,%3}, {%4,%5,%6,%7}, {%8,%9}, {%0,%1,%2,%3};"
        : "+f"(c[0]), "+f"(c[1]), "+f"(c[2]), "+f"(c[3])
        : "r"(a[0]), "r"(a[1]), "r"(a[2]), "r"(a[3]), "r"(b0), "r"(b1));
}

// ---- packed f32x2 ----
__device__ __forceinline__ unsigned long long pack2(float lo, float hi) {
    unsigned long long r;
    asm("mov.b64 %0, {%1, %2};" : "=l"(r) : "f"(lo), "f"(hi));
    return r;
}
__device__ __forceinline__ unsigned long long fma2(unsigned long long a,
                                                   unsigned long long b,
                                                   unsigned long long c) {
    unsigned long long d;
    asm("fma.rn.f32x2 %0, %1, %2, %3;" : "=l"(d) : "l"(a), "l"(b), "l"(c));
    return d;
}
__device__ __forceinline__ float2 unpack2(unsigned long long v) {
    float2 f;
    asm("mov.b64 {%0, %1}, %2;" : "=f"(f.x), "=f"(f.y) : "l"(v));
    return f;
}

// ---------------------------------------------------------------------------
__global__ void reset_kernel() { if (threadIdx.x == 0) g_fixcount = 0; }

// ---------------------------------------------------------------------------
// Prepass A: x -> fp16.  grid = B*D/8/256 = 32768 blocks.
// ---------------------------------------------------------------------------
__global__ __launch_bounds__(256)
void cvt_x(const float* __restrict__ x) {
    size_t i = ((size_t)blockIdx.x * 256 + threadIdx.x) * 8;
    float4 f0 = *(const float4*)(x + i);
    float4 f1 = *(const float4*)(x + i + 4);
    __half2 h0 = __floats2half2_rn(f0.x, f0.y);
    __half2 h1 = __floats2half2_rn(f0.z, f0.w);
    __half2 h2 = __floats2half2_rn(f1.x, f1.y);
    __half2 h3 = __floats2half2_rn(f1.z, f1.w);
    uint4 o;
    o.x = *(uint32_t*)&h0; o.y = *(uint32_t*)&h1;
    o.z = *(uint32_t*)&h2; o.w = *(uint32_t*)&h3;
    *(uint4*)(g_xh + i) = o;
}

// ---------------------------------------------------------------------------
// Prepass B: W1h[n][k] = fp16(W1[k][n])  (transpose + convert)
// ---------------------------------------------------------------------------
__global__ __launch_bounds__(256)
void transpose_W1h(const float* __restrict__ W1) {
    __shared__ float s[32][33];
    const int n0 = blockIdx.x * 32;
    const int k0 = blockIdx.y * 32;
    const int tx = threadIdx.x & 31;
    const int ty = (threadIdx.x >> 5) * 4;
#pragma unroll
    for (int i = 0; i < 4; i++)
        s[ty + i][tx] = W1[(size_t)(k0 + ty + i) * HIDd + n0 + tx];
    __syncthreads();
#pragma unroll
    for (int i = 0; i < 4; i++)
        g_W1h[(size_t)(n0 + ty + i) * Ddim + k0 + tx] = __float2half_rn(s[tx][ty + i]);
}

// ---------------------------------------------------------------------------
// GEMM1: H = silu(x @ W1 + b1), fp16 mma.sync m16n8k16, fp32 accum.
// CTA 128x128, BK=64, 256 thr, warps 4(m) x 2(n), warp tile 32m x 64n.
// grid = (HID/128=16, B/128=128)
// ---------------------------------------------------------------------------
#define BKh 64
#define LDAh 72
#define STAGEH (128 * LDAh)
#define SMEM_G1 (4 * STAGEH * 2)   // bytes

__global__ __launch_bounds__(256, 2)
void gemm1_fp16(const float* __restrict__ b1) {
    extern __shared__ __half smh[];
    const int tid = threadIdx.x;
    const int wid = tid >> 5, lane = tid & 31;
    const int g = lane >> 2, t = lane & 3;
    const int rowBase = blockIdx.y * 128, colBase = blockIdx.x * 128;
    const int wm = (wid & 3) * 32, wn = (wid >> 2) * 64;

    __half* sA0 = smh;
    __half* sA1 = smh + STAGEH;
    __half* sB0 = smh + 2 * STAGEH;
    __half* sB1 = smh + 3 * STAGEH;

    const __half* Ag = g_xh  + (size_t)rowBase * Ddim;
    const __half* Bg = g_W1h + (size_t)colBase * Ddim;

    const int ldR = tid >> 1;
    const int ldC = (tid & 1) * 32;

    float acc[2][8][4];
#pragma unroll
    for (int mt = 0; mt < 2; mt++)
#pragma unroll
        for (int nt = 0; nt < 8; nt++)
#pragma unroll
            for (int r = 0; r < 4; r++) acc[mt][nt][r] = 0.0f;

    uint4 va[4], vb[4];
#pragma unroll
    for (int i = 0; i < 4; i++) {
        va[i] = *(const uint4*)(Ag + (size_t)ldR * Ddim + ldC + i * 8);
        vb[i] = *(const uint4*)(Bg + (size_t)ldR * Ddim + ldC + i * 8);
    }
#pragma unroll
    for (int i = 0; i < 4; i++) {
        *(uint4*)(sA0 + ldR * LDAh + ldC + i * 8) = va[i];
        *(uint4*)(sB0 + ldR * LDAh + ldC + i * 8) = vb[i];
    }
    __syncthreads();

    const int NCHUNK = Ddim / BKh;   // 64
    for (int kc = 0; kc < NCHUNK; kc++) {
        __half* cA = (kc & 1) ? sA1 : sA0;
        __half* cB = (kc & 1) ? sB1 : sB0;
        __half* nA = (kc & 1) ? sA0 : sA1;
        __half* nB = (kc & 1) ? sB0 : sB1;

        if (kc + 1 < NCHUNK) {
            const int k0 = (kc + 1) * BKh;
#pragma unroll
            for (int i = 0; i < 4; i++) {
                va[i] = *(const uint4*)(Ag + (size_t)ldR * Ddim + k0 + ldC + i * 8);
                vb[i] = *(const uint4*)(Bg + (size_t)ldR * Ddim + k0 + ldC + i * 8);
            }
        }

#pragma unroll
        for (int st = 0; st < 4; st++) {
            const int kk = st * 16 + t * 2;
            uint32_t a[2][4];
#pragma unroll
            for (int mt = 0; mt < 2; mt++) {
                const __half* p = cA + (wm + mt * 16 + g) * LDAh + kk;
                a[mt][0] = *(const uint32_t*)p;
                a[mt][1] = *(const uint32_t*)(p + 8 * LDAh);
                a[mt][2] = *(const uint32_t*)(p + 8);
                a[mt][3] = *(const uint32_t*)(p + 8 * LDAh + 8);
            }
#pragma unroll
            for (int nt = 0; nt < 8; nt++) {
                const __half* q = cB + (wn + nt * 8 + g) * LDAh + kk;
                uint32_t b0 = *(const uint32_t*)q;
                uint32_t b1 = *(const uint32_t*)(q + 8);
                mma_fp16(acc[0][nt], a[0], b0, b1);
                mma_fp16(acc[1][nt], a[1], b0, b1);
            }
        }

        if (kc + 1 < NCHUNK) {
#pragma unroll
            for (int i = 0; i < 4; i++) {
                *(uint4*)(nA + ldR * LDAh + ldC + i * 8) = va[i];
                *(uint4*)(nB + ldR * LDAh + ldC + i * 8) = vb[i];
            }
        }
        __syncthreads();
    }

    // epilogue: bias + silu -> g_H
#pragma unroll
    for (int nt = 0; nt < 8; nt++) {
        const int n0 = colBase + wn + nt * 8 + t * 2;
        const float bs0 = b1[n0];
        const float bs1 = b1[n0 + 1];
#pragma unroll
        for (int mt = 0; mt < 2; mt++) {
            const int m0 = rowBase + wm + mt * 16 + g;
            float2 o0, o1;
            o0.x = silu_f(acc[mt][nt][0] + bs0);
            o0.y = silu_f(acc[mt][nt][1] + bs1);
            o1.x = silu_f(acc[mt][nt][2] + bs0);
            o1.y = silu_f(acc[mt][nt][3] + bs1);
            *(float2*)(g_H + (size_t)m0 * HIDd + n0)       = o0;
            *(float2*)(g_H + (size_t)(m0 + 8) * HIDd + n0) = o1;
        }
    }
}

// ---------------------------------------------------------------------------
// Router: logits = H @ W2 + b2; top-2 / softmax / prob partials / tie flags.
// ---------------------------------------------------------------------------
__global__ __launch_bounds__(256)
void router_kernel(const float* __restrict__ W2,
                   const float* __restrict__ b2,
                   float* __restrict__ outW,
                   float* __restrict__ outI) {
    __shared__ float sW2[128][Ed];
    __shared__ float sH[32][128];
    __shared__ float sProb[32][Ed];

    const int tid  = threadIdx.x;
    const int warp = tid >> 5;
    const int lane = tid & 31;
    const int rowBase = blockIdx.x * 32;

    unsigned long long acc[4] = {0ULL, 0ULL, 0ULL, 0ULL};

    for (int kc = 0; kc < HIDd; kc += 128) {
        __syncthreads();
#pragma unroll
        for (int i = 0; i < 8; i++) {
            int idx = tid + 256 * i;
            int r = idx >> 4, c4 = (idx & 15) * 4;
            *(float4*)&sW2[r][c4] = *(const float4*)&W2[(size_t)(kc + r) * Ed + c4];
        }
#pragma unroll
        for (int i = 0; i < 4; i++) {
            int idx = tid + 256 * i;
            int r = idx >> 5, c = (idx & 31) * 4;
            *(float4*)&sH[r][c] = *(const float4*)&g_H[(size_t)(rowBase + r) * HIDd + kc + c];
        }
        __syncthreads();

#pragma unroll 2
        for (int k4 = 0; k4 < 32; k4++) {
            unsigned long long wv0 = *(const unsigned long long*)&sW2[k4 * 4 + 0][lane * 2];
            unsigned long long wv1 = *(const unsigned long long*)&sW2[k4 * 4 + 1][lane * 2];
            unsigned long long wv2 = *(const unsigned long long*)&sW2[k4 * 4 + 2][lane * 2];
            unsigned long long wv3 = *(const unsigned long long*)&sW2[k4 * 4 + 3][lane * 2];
#pragma unroll
            for (int r = 0; r < 4; r++) {
                float4 h4 = *(const float4*)&sH[warp * 4 + r][k4 * 4];
                acc[r] = fma2(pack2(h4.x, h4.x), wv0, acc[r]);
                acc[r] = fma2(pack2(h4.y, h4.y), wv1, acc[r]);
                acc[r] = fma2(pack2(h4.z, h4.z), wv2, acc[r]);
                acc[r] = fma2(pack2(h4.w, h4.w), wv3, acc[r]);
            }
        }
    }

    const float b2a = b2[lane * 2];
    const float b2b = b2[lane * 2 + 1];

#pragma unroll
    for (int r = 0; r < 4; r++) {
        const int lrow = warp * 4 + r;
        float2 av = unpack2(acc[r]);
        float l0 = av.x + b2a;
        float l1 = av.y + b2b;
        const int id0 = lane * 2, id1 = lane * 2 + 1;

        float bvv, sv; int bi, si;
        if (l0 >= l1) { bvv = l0; bi = id0; sv = l1; si = id1; }
        else          { bvv = l1; bi = id1; sv = l0; si = id0; }

        float v1 = bvv; int i1 = bi;
#pragma unroll
        for (int off = 16; off; off >>= 1) {
            float ov = __shfl_down_sync(0xffffffffu, v1, off);
            int   oi = __shfl_down_sync(0xffffffffu, i1, off);
            if (ov > v1 || (ov == v1 && oi < i1)) { v1 = ov; i1 = oi; }
        }
        v1 = __shfl_sync(0xffffffffu, v1, 0);
        i1 = __shfl_sync(0xffffffffu, i1, 0);

        float cv; int ci;
        if (bi == i1) { cv = sv; ci = si; } else { cv = bvv; ci = bi; }
        float v2 = cv; int i2 = ci;
#pragma unroll
        for (int off = 16; off; off >>= 1) {
            float ov = __shfl_down_sync(0xffffffffu, v2, off);
            int   oi = __shfl_down_sync(0xffffffffu, i2, off);
            if (ov > v2 || (ov == v2 && oi < i2)) { v2 = ov; i2 = oi; }
        }
        v2 = __shfl_sync(0xffffffffu, v2, 0);
        i2 = __shfl_sync(0xffffffffu, i2, 0);

        // third-best value (for tie flagging)
        float v3 = -1e30f;
        if (id0 != i1 && id0 != i2) v3 = l0;
        if (id1 != i1 && id1 != i2 && l1 > v3) v3 = l1;
#pragma unroll
        for (int off = 16; off; off >>= 1) {
            float ov = __shfl_down_sync(0xffffffffu, v3, off);
            if (ov > v3) v3 = ov;
        }

        float p0 = expf(l0 - v1);
        float p1 = expf(l1 - v1);
        float ssum = p0 + p1;
#pragma unroll
        for (int off = 16; off; off >>= 1) ssum += __shfl_down_sync(0xffffffffu, ssum, off);
        ssum = __shfl_sync(0xffffffffu, ssum, 0);
        float inv = 1.0f / ssum;
        sProb[lrow][lane * 2]     = p0 * inv;
        sProb[lrow][lane * 2 + 1] = p1 * inv;

        if (lane == 0) {
            float d = expf(v2 - v1);
            float w0 = 1.0f / (1.0f + d);
            float w1 = d / (1.0f + d);
            size_t gb = (size_t)(rowBase + lrow);
            outW[gb * 2]     = w0;
            outW[gb * 2 + 1] = w1;
            outI[gb * 2]     = (float)i1;
            outI[gb * 2 + 1] = (float)i2;
            g_top1[gb]       = i1;
            if ((v1 - v2) < TAU || (v2 - v3) < TAU) {
                int pos = atomicAdd(&g_fixcount, 1);
                if (pos < FIXCAP) g_fixlist[pos] = (int)gb;
            }
        }
    }
    __syncthreads();

    if (tid < Ed) {
        float ps = 0.0f;
#pragma unroll
        for (int r = 0; r < 32; r++) ps += sProb[r][tid];
        g_pprob[(size_t)blockIdx.x * Ed + tid] = ps;
    }
}

// ---------------------------------------------------------------------------
// Fixup stage 1: exact fp32 h for flagged rows.
// grid = (FIXCAP/16=512 row-groups, 16 col-slices of 128); 128 thr.
// smem: 16 rows x 1024 k-quarter = 64KB.
// ---------------------------------------------------------------------------
__global__ __launch_bounds__(128)
void fixup_h(const float* __restrict__ x,
             const float* __restrict__ W1,
             const float* __restrict__ b1) {
    extern __shared__ float sX[];   // 16 * 1024
    int cnt = g_fixcount; if (cnt > FIXCAP) cnt = FIXCAP;
    if (blockIdx.x * 16 >= cnt) return;
    const int tid = threadIdx.x;
    const int col = blockIdx.y * 128 + tid;

    int rows[16];
#pragma unroll
    for (int r = 0; r < 16; r++) {
        int gi = blockIdx.x * 16 + r;
        rows[r] = g_fixlist[gi < cnt ? gi : cnt - 1];
    }

    unsigned long long acc2[8];
#pragma unroll
    for (int r = 0; r < 8; r++) acc2[r] = 0ULL;

    for (int q = 0; q < 4; q++) {
        __syncthreads();
        for (int idx = tid; idx < 16 * 1024; idx += 128) {
            int r = idx >> 10, kk = idx & 1023;
            sX[idx] = x[(size_t)rows[r] * Ddim + q * 1024 + kk];
        }
        __syncthreads();
        for (int kk = 0; kk < 1024; kk += 4) {
            const size_t kb = (size_t)(q * 1024 + kk) * HIDd + col;
            float w0 = W1[kb];
            float w1 = W1[kb + HIDd];
            float w2 = W1[kb + 2 * HIDd];
            float w3 = W1[kb + 3 * HIDd];
            unsigned long long wq0 = pack2(w0, w0);
            unsigned long long wq1 = pack2(w1, w1);
            unsigned long long wq2 = pack2(w2, w2);
            unsigned long long wq3 = pack2(w3, w3);
#pragma unroll
            for (int r2 = 0; r2 < 8; r2++) {
                float4 xa = *(const float4*)&sX[(2 * r2) * 1024 + kk];
                float4 xb = *(const float4*)&sX[(2 * r2 + 1) * 1024 + kk];
                acc2[r2] = fma2(pack2(xa.x, xb.x), wq0, acc2[r2]);
                acc2[r2] = fma2(pack2(xa.y, xb.y), wq1, acc2[r2]);
                acc2[r2] = fma2(pack2(xa.z, xb.z), wq2, acc2[r2]);
                acc2[r2] = fma2(pack2(xa.w, xb.w), wq3, acc2[r2]);
            }
        }
    }
    const float bb = b1[col];
#pragma unroll
    for (int r2 = 0; r2 < 8; r2++) {
        float2 v = unpack2(acc2[r2]);
        int gi0 = blockIdx.x * 16 + 2 * r2;
        int gi1 = gi0 + 1;
        if (gi0 < cnt) g_H[(size_t)rows[2 * r2]     * HIDd + col] = silu_f(v.x + bb);
        if (gi1 < cnt) g_H[(size_t)rows[2 * r2 + 1] * HIDd + col] = silu_f(v.y + bb);
    }
}

// ---------------------------------------------------------------------------
// Fixup stage 2: exact logits + top2 + weights for flagged rows.
// ---------------------------------------------------------------------------
__global__ __launch_bounds__(256)
void fixup_logits(const float* __restrict__ W2,
                  const float* __restrict__ b2,
                  float* __restrict__ outW,
                  float* __restrict__ outI) {
    int cnt = g_fixcount; if (cnt > FIXCAP) cnt = FIXCAP;
    const int fi = blockIdx.x;
    if (fi >= cnt) return;
    const int row = g_fixlist[fi];
    const int tid = threadIdx.x;
    const int e = tid & 63, q = tid >> 6;
    __shared__ float part[4][Ed];
    __shared__ float sLog[Ed];

    float a = 0.0f;
    const float* hrow = g_H + (size_t)row * HIDd;
    for (int k = q * 512; k < (q + 1) * 512; k++)
        a = fmaf(hrow[k], W2[(size_t)k * Ed + e], a);
    part[q][e] = a;
    __syncthreads();
    if (tid < Ed)
        sLog[tid] = part[0][tid] + part[1][tid] + part[2][tid] + part[3][tid] + b2[tid];
    __syncthreads();
    if (tid == 0) {
        float v1 = -1e30f, v2 = -1e30f; int i1 = 0, i2 = 0;
        for (int j = 0; j < Ed; j++) {
            float v = sLog[j];
            if (v > v1)      { v2 = v1; i2 = i1; v1 = v; i1 = j; }
            else if (v > v2) { v2 = v;  i2 = j; }
        }
        float d = expf(v2 - v1);
        outW[(size_t)row * 2]     = 1.0f / (1.0f + d);
        outW[(size_t)row * 2 + 1] = d / (1.0f + d);
        outI[(size_t)row * 2]     = (float)i1;
        outI[(size_t)row * 2 + 1] = (float)i2;
        g_top1[row] = i1;
    }
}

// ---------------------------------------------------------------------------
// Final: freq from g_top1, aux = E * sum freq_e * avgprob_e.
// ---------------------------------------------------------------------------
__global__ __launch_bounds__(256)
void aux_final(float* __restrict__ outAux) {
    __shared__ int   hist[Ed];
    __shared__ float term[Ed];
    const int tid = threadIdx.x;
    if (tid < Ed) hist[tid] = 0;
    __syncthreads();
    for (int r = tid; r < Bdim; r += 256)
        atomicAdd(&hist[g_top1[r]], 1);
    __syncthreads();
    if (tid < Ed) {
        float p = 0.0f;
        for (int b = 0; b < 512; b++) p += g_pprob[b * Ed + tid];
        term[tid] = ((float)hist[tid] * (1.0f / (float)Bdim)) *
                    (p * (1.0f / (float)Bdim));
    }
    __syncthreads();
    if (tid == 0) {
        float s = 0.0f;
        for (int e = 0; e < Ed; e++) s += term[e];
        outAux[0] = (float)Ed * s;
    }
}

// ---------------------------------------------------------------------------
extern "C" void kernel_launch(void* const* d_in, const int* in_sizes, int n_in,
                              void* d_out, int out_size) {
    const float* x  = (const float*)d_in[0];
    const float* W1 = (const float*)d_in[1];
    const float* b1 = (const float*)d_in[2];
    const float* W2 = (const float*)d_in[3];
    const float* b2 = (const float*)d_in[4];
    float* out = (float*)d_out;

    float* outW   = out;
    float* outI   = out + 2 * Bdim;
    float* outAux = out + 4 * Bdim;

    cudaFuncSetAttribute(gemm1_fp16, cudaFuncAttributeMaxDynamicSharedMemorySize,
                         SMEM_G1);
    cudaFuncSetAttribute(fixup_h, cudaFuncAttributeMaxDynamicSharedMemorySize,
                         16 * 1024 * (int)sizeof(float));

    reset_kernel<<<1, 32>>>();
    cvt_x<<<(int)(((size_t)Bdim * Ddim) / 8 / 256), 256>>>(x);
    transpose_W1h<<<dim3(HIDd / 32, Ddim / 32), 256>>>(W1);
    gemm1_fp16<<<dim3(HIDd / 128, Bdim / 128), 256, SMEM_G1>>>(b1);
    router_kernel<<<Bdim / 32, 256>>>(W2, b2, outW, outI);
    fixup_h<<<dim3(FIXCAP / 16, 16), 128, 16 * 1024 * sizeof(float)>>>(x, W1, b1);
    fixup_logits<<<FIXCAP, 256>>>(W2, b2, outW, outI);
    aux_final<<<1, 256>>>(outAux);
}

// round 6
// speedup vs baseline: 3.0126x; 1.6305x over previous
#include <cuda_runtime.h>
#include <cuda_fp16.h>
#include <cstdint>
#include <math.h>

// ---------------------------------------------------------------------------
// ExpertRouter: h = silu(x@W1+b1); logits = h@W2+b2; top-2 softmax + aux loss.
// B=16384, D=4096, HID=2048, E=64.
// GEMM1: fp16 mma.sync m16n8k16, cp.async 4-stage pipeline, ldmatrix frags.
// Rows with top-2/3 gap < TAU recomputed exactly in fp32 (indices exact).
// Output layout (f32): [weights B*2 | top_idx(as float) B*2 | aux].
// ---------------------------------------------------------------------------

#define Bdim 16384
#define Ddim 4096
#define HIDd 2048
#define Ed   64
#define TAU  3e-3f
#define FIXCAP 4096

__device__ float  g_H[(size_t)Bdim * HIDd];     // 134 MB intermediate h (fp32)
__device__ __half g_xh[(size_t)Bdim * Ddim];    // 134 MB x in fp16
__device__ __half g_W1h[(size_t)HIDd * Ddim];   // 16.8 MB W1^T in fp16
__device__ float  g_pprob[512 * Ed];
__device__ int    g_top1[Bdim];
__device__ int    g_fixcount;
__device__ int    g_fixlist[FIXCAP];

// ---- helpers ----
__device__ __forceinline__ float silu_f(float v) { return v / (1.0f + expf(-v)); }

__device__ __forceinline__ uint32_t smem_u32(const void* p) {
    uint32_t a;
    asm("{ .reg .u64 t; cvta.to.shared.u64 t, %1; cvt.u32.u64 %0, t; }" : "=r"(a) : "l"(p));
    return a;
}
__device__ __forceinline__ void cp_async16(uint32_t saddr, const void* gaddr) {
    asm volatile("cp.async.cg.shared.global [%0], [%1], 16;" :: "r"(saddr), "l"(gaddr));
}
__device__ __forceinline__ void cp_commit() {
    asm volatile("cp.async.commit_group;");
}
template <int N>
__device__ __forceinline__ void cp_wait() {
    asm volatile("cp.async.wait_group %0;" :: "n"(N));
}
__device__ __forceinline__ void ldsm_x4(uint32_t r[4], uint32_t saddr) {
    asm volatile("ldmatrix.sync.aligned.m8n8.x4.shared.b16 {%0,%1,%2,%3}, [%4];"
                 : "=r"(r[0]), "=r"(r[1]), "=r"(r[2]), "=r"(r[3]) : "r"(saddr));
}
__device__ __forceinline__ void mma_fp16(float c[4], const uint32_t a[4],
                                         uint32_t b0, uint32_t b1) {
    asm("mma.sync.aligned.m16n8k16.row.col.f32.f16.f16.f32 "
        "{%0,%1,%2,%3}, {%4,%5,%6,%7}, {%8,%9}, {%0,%1,%2,%3};"
        : "+f"(c[0]), "+f"(c[1]), "+f"(c[2]), "+f"(c[3])
        : "r"(a[0]), "r"(a[1]), "r"(a[2]), "r"(a[3]), "r"(b0), "r"(b1));
}

// ---- packed f32x2 ----
__device__ __forceinline__ unsigned long long pack2(float lo, float hi) {
    unsigned long long r;
    asm("mov.b64 %0, {%1, %2};" : "=l"(r) : "f"(lo), "f"(hi));
    return r;
}
__device__ __forceinline__ unsigned long long fma2(unsigned long long a,
                                                   unsigned long long b,
                                                   unsigned long long c) {
    unsigned long long d;
    asm("fma.rn.f32x2 %0, %1, %2, %3;" : "=l"(d) : "l"(a), "l"(b), "l"(c));
    return d;
}
__device__ __forceinline__ float2 unpack2(unsigned long long v) {
    float2 f;
    asm("mov.b64 {%0, %1}, %2;" : "=f"(f.x), "=f"(f.y) : "l"(v));
    return f;
}

// ---------------------------------------------------------------------------
__global__ void reset_kernel() { if (threadIdx.x == 0) g_fixcount = 0; }

// ---------------------------------------------------------------------------
__global__ __launch_bounds__(256)
void cvt_x(const float* __restrict__ x) {
    size_t i = ((size_t)blockIdx.x * 256 + threadIdx.x) * 8;
    float4 f0 = *(const float4*)(x + i);
    float4 f1 = *(const float4*)(x + i + 4);
    __half2 h0 = __floats2half2_rn(f0.x, f0.y);
    __half2 h1 = __floats2half2_rn(f0.z, f0.w);
    __half2 h2 = __floats2half2_rn(f1.x, f1.y);
    __half2 h3 = __floats2half2_rn(f1.z, f1.w);
    uint4 o;
    o.x = *(uint32_t*)&h0; o.y = *(uint32_t*)&h1;
    o.z = *(uint32_t*)&h2; o.w = *(uint32_t*)&h3;
    *(uint4*)(g_xh + i) = o;
}

// ---------------------------------------------------------------------------
__global__ __launch_bounds__(256)
void transpose_W1h(const float* __restrict__ W1) {
    __shared__ float s[32][33];
    const int n0 = blockIdx.x * 32;
    const int k0 = blockIdx.y * 32;
    const int tx = threadIdx.x & 31;
    const int ty = (threadIdx.x >> 5) * 4;
#pragma unroll
    for (int i = 0; i < 4; i++)
        s[ty + i][tx] = W1[(size_t)(k0 + ty + i) * HIDd + n0 + tx];
    __syncthreads();
#pragma unroll
    for (int i = 0; i < 4; i++)
        g_W1h[(size_t)(n0 + ty + i) * Ddim + k0 + tx] = __float2half_rn(s[tx][ty + i]);
}

// ---------------------------------------------------------------------------
// GEMM1: H = silu(x @ W1 + b1), fp16 mma, cp.async 4-stage, ldmatrix frags.
// CTA 128x128, BK=64, 256 thr, warps 4(m) x 2(n), warp tile 32m x 64n.
// ---------------------------------------------------------------------------
#define BKh 64
#define LDAh 72                        // halves per row (144 B, 16B-multiple)
#define ARRH (128 * LDAh)              // 9216 halves per array (A or B)
#define STG_H (2 * ARRH)               // halves per stage
#define NSTAGE 4
#define SMEM_G1 (NSTAGE * STG_H * 2)   // 147456 bytes

__global__ __launch_bounds__(256, 1)
void gemm1_fp16(const float* __restrict__ b1) {
    extern __shared__ __half smh[];
    const uint32_t sbase = smem_u32(smh);

    const int tid = threadIdx.x;
    const int wid = tid >> 5, lane = tid & 31;
    const int rowBase = blockIdx.y * 128, colBase = blockIdx.x * 128;
    const int wm = (wid & 3) * 32, wn = (wid >> 2) * 64;

    const __half* Ag = g_xh  + (size_t)rowBase * Ddim;
    const __half* Bg = g_W1h + (size_t)colBase * Ddim;

    // cp.async mapping: 2048 16B-chunks per stage, 8 per thread
    int ld_arr[8], ld_row[8], ld_off[8];
    uint32_t ld_saddr[8];
#pragma unroll
    for (int i = 0; i < 8; i++) {
        int c = tid + 256 * i;
        ld_arr[i] = c >> 10;
        int rem = c & 1023;
        ld_row[i] = rem >> 3;
        ld_off[i] = (rem & 7) * 8;        // halves
        ld_saddr[i] = sbase + (uint32_t)(ld_arr[i] * ARRH + ld_row[i] * LDAh + ld_off[i]) * 2;
    }

    // ldmatrix lane address components (byte offsets within stage)
    const int a_m   = wm + (lane & 15);
    const int a_k   = ((lane >> 4) & 1) * 8;
    const uint32_t aOff0 = (uint32_t)(a_m * LDAh + a_k) * 2;            // mt=0
    const uint32_t aOff1 = (uint32_t)((a_m + 16) * LDAh + a_k) * 2;     // mt=1
    const int b_k   = ((lane >> 3) & 1) * 8;
    uint32_t bOff[4];
#pragma unroll
    for (int p = 0; p < 4; p++) {
        int n = wn + p * 16 + (lane & 7) + ((lane >> 4) & 1) * 8;
        bOff[p] = (uint32_t)(ARRH + n * LDAh + b_k) * 2;
    }

    float acc[2][8][4];
#pragma unroll
    for (int mt = 0; mt < 2; mt++)
#pragma unroll
        for (int nt = 0; nt < 8; nt++)
#pragma unroll
            for (int r = 0; r < 4; r++) acc[mt][nt][r] = 0.0f;

    const int NCHUNK = Ddim / BKh;     // 64

    // prologue: issue stages 0..2
#pragma unroll
    for (int kc = 0; kc < NSTAGE - 1; kc++) {
        const int k0 = kc * BKh;
        const uint32_t sb = (uint32_t)(kc & 3) * STG_H * 2;
#pragma unroll
        for (int i = 0; i < 8; i++) {
            const __half* g = (ld_arr[i] ? Bg : Ag) +
                              (size_t)ld_row[i] * Ddim + k0 + ld_off[i];
            cp_async16(ld_saddr[i] + sb, g);
        }
        cp_commit();
    }

    for (int kc = 0; kc < NCHUNK; kc++) {
        cp_wait<NSTAGE - 2>();
        __syncthreads();

        // issue stage kc+3
        if (kc + NSTAGE - 1 < NCHUNK) {
            const int k0 = (kc + NSTAGE - 1) * BKh;
            const uint32_t sb = (uint32_t)((kc + NSTAGE - 1) & 3) * STG_H * 2;
#pragma unroll
            for (int i = 0; i < 8; i++) {
                const __half* g = (ld_arr[i] ? Bg : Ag) +
                                  (size_t)ld_row[i] * Ddim + k0 + ld_off[i];
                cp_async16(ld_saddr[i] + sb, g);
            }
            cp_commit();
        }

        // compute on stage kc
        const uint32_t sb = sbase + (uint32_t)(kc & 3) * STG_H * 2;
#pragma unroll
        for (int st = 0; st < 4; st++) {
            const uint32_t kb = (uint32_t)(st * 16) * 2;   // byte offset of k-step
            uint32_t a0[4], a1[4];
            ldsm_x4(a0, sb + aOff0 + kb);
            ldsm_x4(a1, sb + aOff1 + kb);
#pragma unroll
            for (int p = 0; p < 4; p++) {
                uint32_t bfr[4];
                ldsm_x4(bfr, sb + bOff[p] + kb);
                mma_fp16(acc[0][2 * p],     a0, bfr[0], bfr[1]);
                mma_fp16(acc[1][2 * p],     a1, bfr[0], bfr[1]);
                mma_fp16(acc[0][2 * p + 1], a0, bfr[2], bfr[3]);
                mma_fp16(acc[1][2 * p + 1], a1, bfr[2], bfr[3]);
            }
        }
        __syncthreads();
    }

    // epilogue: bias + silu -> g_H
    const int g = lane >> 2, t = lane & 3;
#pragma unroll
    for (int nt = 0; nt < 8; nt++) {
        const int n0 = colBase + wn + nt * 8 + t * 2;
        const float bs0 = b1[n0];
        const float bs1 = b1[n0 + 1];
#pragma unroll
        for (int mt = 0; mt < 2; mt++) {
            const int m0 = rowBase + wm + mt * 16 + g;
            float2 o0, o1;
            o0.x = silu_f(acc[mt][nt][0] + bs0);
            o0.y = silu_f(acc[mt][nt][1] + bs1);
            o1.x = silu_f(acc[mt][nt][2] + bs0);
            o1.y = silu_f(acc[mt][nt][3] + bs1);
            *(float2*)(g_H + (size_t)m0 * HIDd + n0)       = o0;
            *(float2*)(g_H + (size_t)(m0 + 8) * HIDd + n0) = o1;
        }
    }
}

// ---------------------------------------------------------------------------
// Router: logits = H @ W2 + b2; top-2 / softmax / prob partials / tie flags.
// ---------------------------------------------------------------------------
__global__ __launch_bounds__(256)
void router_kernel(const float* __restrict__ W2,
                   const float* __restrict__ b2,
                   float* __restrict__ outW,
                   float* __restrict__ outI) {
    __shared__ float sW2[128][Ed];
    __shared__ float sH[32][128];
    __shared__ float sProb[32][Ed];

    const int tid  = threadIdx.x;
    const int warp = tid >> 5;
    const int lane = tid & 31;
    const int rowBase = blockIdx.x * 32;

    unsigned long long acc[4] = {0ULL, 0ULL, 0ULL, 0ULL};

    for (int kc = 0; kc < HIDd; kc += 128) {
        __syncthreads();
#pragma unroll
        for (int i = 0; i < 8; i++) {
            int idx = tid + 256 * i;
            int r = idx >> 4, c4 = (idx & 15) * 4;
            *(float4*)&sW2[r][c4] = *(const float4*)&W2[(size_t)(kc + r) * Ed + c4];
        }
#pragma unroll
        for (int i = 0; i < 4; i++) {
            int idx = tid + 256 * i;
            int r = idx >> 5, c = (idx & 31) * 4;
            *(float4*)&sH[r][c] = *(const float4*)&g_H[(size_t)(rowBase + r) * HIDd + kc + c];
        }
        __syncthreads();

#pragma unroll 2
        for (int k4 = 0; k4 < 32; k4++) {
            unsigned long long wv0 = *(const unsigned long long*)&sW2[k4 * 4 + 0][lane * 2];
            unsigned long long wv1 = *(const unsigned long long*)&sW2[k4 * 4 + 1][lane * 2];
            unsigned long long wv2 = *(const unsigned long long*)&sW2[k4 * 4 + 2][lane * 2];
            unsigned long long wv3 = *(const unsigned long long*)&sW2[k4 * 4 + 3][lane * 2];
#pragma unroll
            for (int r = 0; r < 4; r++) {
                float4 h4 = *(const float4*)&sH[warp * 4 + r][k4 * 4];
                acc[r] = fma2(pack2(h4.x, h4.x), wv0, acc[r]);
                acc[r] = fma2(pack2(h4.y, h4.y), wv1, acc[r]);
                acc[r] = fma2(pack2(h4.z, h4.z), wv2, acc[r]);
                acc[r] = fma2(pack2(h4.w, h4.w), wv3, acc[r]);
            }
        }
    }

    const float b2a = b2[lane * 2];
    const float b2b = b2[lane * 2 + 1];

#pragma unroll
    for (int r = 0; r < 4; r++) {
        const int lrow = warp * 4 + r;
        float2 av = unpack2(acc[r]);
        float l0 = av.x + b2a;
        float l1 = av.y + b2b;
        const int id0 = lane * 2, id1 = lane * 2 + 1;

        float bvv, sv; int bi, si;
        if (l0 >= l1) { bvv = l0; bi = id0; sv = l1; si = id1; }
        else          { bvv = l1; bi = id1; sv = l0; si = id0; }

        float v1 = bvv; int i1 = bi;
#pragma unroll
        for (int off = 16; off; off >>= 1) {
            float ov = __shfl_down_sync(0xffffffffu, v1, off);
            int   oi = __shfl_down_sync(0xffffffffu, i1, off);
            if (ov > v1 || (ov == v1 && oi < i1)) { v1 = ov; i1 = oi; }
        }
        v1 = __shfl_sync(0xffffffffu, v1, 0);
        i1 = __shfl_sync(0xffffffffu, i1, 0);

        float cv; int ci;
        if (bi == i1) { cv = sv; ci = si; } else { cv = bvv; ci = bi; }
        float v2 = cv; int i2 = ci;
#pragma unroll
        for (int off = 16; off; off >>= 1) {
            float ov = __shfl_down_sync(0xffffffffu, v2, off);
            int   oi = __shfl_down_sync(0xffffffffu, i2, off);
            if (ov > v2 || (ov == v2 && oi < i2)) { v2 = ov; i2 = oi; }
        }
        v2 = __shfl_sync(0xffffffffu, v2, 0);
        i2 = __shfl_sync(0xffffffffu, i2, 0);

        float v3 = -1e30f;
        if (id0 != i1 && id0 != i2) v3 = l0;
        if (id1 != i1 && id1 != i2 && l1 > v3) v3 = l1;
#pragma unroll
        for (int off = 16; off; off >>= 1) {
            float ov = __shfl_down_sync(0xffffffffu, v3, off);
            if (ov > v3) v3 = ov;
        }

        float p0 = expf(l0 - v1);
        float p1 = expf(l1 - v1);
        float ssum = p0 + p1;
#pragma unroll
        for (int off = 16; off; off >>= 1) ssum += __shfl_down_sync(0xffffffffu, ssum, off);
        ssum = __shfl_sync(0xffffffffu, ssum, 0);
        float inv = 1.0f / ssum;
        sProb[lrow][lane * 2]     = p0 * inv;
        sProb[lrow][lane * 2 + 1] = p1 * inv;

        if (lane == 0) {
            float d = expf(v2 - v1);
            float w0 = 1.0f / (1.0f + d);
            float w1 = d / (1.0f + d);
            size_t gb = (size_t)(rowBase + lrow);
            outW[gb * 2]     = w0;
            outW[gb * 2 + 1] = w1;
            outI[gb * 2]     = (float)i1;
            outI[gb * 2 + 1] = (float)i2;
            g_top1[gb]       = i1;
            if ((v1 - v2) < TAU || (v2 - v3) < TAU) {
                int pos = atomicAdd(&g_fixcount, 1);
                if (pos < FIXCAP) g_fixlist[pos] = (int)gb;
            }
        }
    }
    __syncthreads();

    if (tid < Ed) {
        float ps = 0.0f;
#pragma unroll
        for (int r = 0; r < 32; r++) ps += sProb[r][tid];
        g_pprob[(size_t)blockIdx.x * Ed + tid] = ps;
    }
}

// ---------------------------------------------------------------------------
// Fixup stage 1: exact fp32 h for flagged rows (16 rows/group, 16 col-slices).
// ---------------------------------------------------------------------------
__global__ __launch_bounds__(128)
void fixup_h(const float* __restrict__ x,
             const float* __restrict__ W1,
             const float* __restrict__ b1) {
    extern __shared__ float sX[];   // 16 * 1024 floats
    int cnt = g_fixcount; if (cnt > FIXCAP) cnt = FIXCAP;
    if (blockIdx.x * 16 >= cnt) return;
    const int tid = threadIdx.x;
    const int col = blockIdx.y * 128 + tid;

    int rows[16];
#pragma unroll
    for (int r = 0; r < 16; r++) {
        int gi = blockIdx.x * 16 + r;
        rows[r] = g_fixlist[gi < cnt ? gi : cnt - 1];
    }

    unsigned long long acc2[8];
#pragma unroll
    for (int r = 0; r < 8; r++) acc2[r] = 0ULL;

    for (int q = 0; q < 4; q++) {
        __syncthreads();
        for (int idx = tid; idx < 16 * 1024; idx += 128) {
            int r = idx >> 10, kk = idx & 1023;
            sX[idx] = x[(size_t)rows[r] * Ddim + q * 1024 + kk];
        }
        __syncthreads();
        for (int kk = 0; kk < 1024; kk += 4) {
            const size_t kb = (size_t)(q * 1024 + kk) * HIDd + col;
            float w0 = W1[kb];
            float w1 = W1[kb + HIDd];
            float w2 = W1[kb + 2 * HIDd];
            float w3 = W1[kb + 3 * HIDd];
            unsigned long long wq0 = pack2(w0, w0);
            unsigned long long wq1 = pack2(w1, w1);
            unsigned long long wq2 = pack2(w2, w2);
            unsigned long long wq3 = pack2(w3, w3);
#pragma unroll
            for (int r2 = 0; r2 < 8; r2++) {
                float4 xa = *(const float4*)&sX[(2 * r2) * 1024 + kk];
                float4 xb = *(const float4*)&sX[(2 * r2 + 1) * 1024 + kk];
                acc2[r2] = fma2(pack2(xa.x, xb.x), wq0, acc2[r2]);
                acc2[r2] = fma2(pack2(xa.y, xb.y), wq1, acc2[r2]);
                acc2[r2] = fma2(pack2(xa.z, xb.z), wq2, acc2[r2]);
                acc2[r2] = fma2(pack2(xa.w, xb.w), wq3, acc2[r2]);
            }
        }
    }
    const float bb = b1[col];
#pragma unroll
    for (int r2 = 0; r2 < 8; r2++) {
        float2 v = unpack2(acc2[r2]);
        int gi0 = blockIdx.x * 16 + 2 * r2;
        int gi1 = gi0 + 1;
        if (gi0 < cnt) g_H[(size_t)rows[2 * r2]     * HIDd + col] = silu_f(v.x + bb);
        if (gi1 < cnt) g_H[(size_t)rows[2 * r2 + 1] * HIDd + col] = silu_f(v.y + bb);
    }
}

// ---------------------------------------------------------------------------
// Fixup stage 2: exact logits + top2 + weights for flagged rows.
// ---------------------------------------------------------------------------
__global__ __launch_bounds__(256)
void fixup_logits(const float* __restrict__ W2,
                  const float* __restrict__ b2,
                  float* __restrict__ outW,
                  float* __restrict__ outI) {
    int cnt = g_fixcount; if (cnt > FIXCAP) cnt = FIXCAP;
    const int fi = blockIdx.x;
    if (fi >= cnt) return;
    const int row = g_fixlist[fi];
    const int tid = threadIdx.x;
    const int e = tid & 63, q = tid >> 6;
    __shared__ float part[4][Ed];
    __shared__ float sLog[Ed];

    float a = 0.0f;
    const float* hrow = g_H + (size_t)row * HIDd;
    for (int k = q * 512; k < (q + 1) * 512; k++)
        a = fmaf(hrow[k], W2[(size_t)k * Ed + e], a);
    part[q][e] = a;
    __syncthreads();
    if (tid < Ed)
        sLog[tid] = part[0][tid] + part[1][tid] + part[2][tid] + part[3][tid] + b2[tid];
    __syncthreads();
    if (tid == 0) {
        float v1 = -1e30f, v2 = -1e30f; int i1 = 0, i2 = 0;
        for (int j = 0; j < Ed; j++) {
            float v = sLog[j];
            if (v > v1)      { v2 = v1; i2 = i1; v1 = v; i1 = j; }
            else if (v > v2) { v2 = v;  i2 = j; }
        }
        float d = expf(v2 - v1);
        outW[(size_t)row * 2]     = 1.0f / (1.0f + d);
        outW[(size_t)row * 2 + 1] = d / (1.0f + d);
        outI[(size_t)row * 2]     = (float)i1;
        outI[(size_t)row * 2 + 1] = (float)i2;
        g_top1[row] = i1;
    }
}

// ---------------------------------------------------------------------------
__global__ __launch_bounds__(256)
void aux_final(float* __restrict__ outAux) {
    __shared__ int   hist[Ed];
    __shared__ float term[Ed];
    const int tid = threadIdx.x;
    if (tid < Ed) hist[tid] = 0;
    __syncthreads();
    for (int r = tid; r < Bdim; r += 256)
        atomicAdd(&hist[g_top1[r]], 1);
    __syncthreads();
    if (tid < Ed) {
        float p = 0.0f;
        for (int b = 0; b < 512; b++) p += g_pprob[b * Ed + tid];
        term[tid] = ((float)hist[tid] * (1.0f / (float)Bdim)) *
                    (p * (1.0f / (float)Bdim));
    }
    __syncthreads();
    if (tid == 0) {
        float s = 0.0f;
        for (int e = 0; e < Ed; e++) s += term[e];
        outAux[0] = (float)Ed * s;
    }
}

// ---------------------------------------------------------------------------
extern "C" void kernel_launch(void* const* d_in, const int* in_sizes, int n_in,
                              void* d_out, int out_size) {
    const float* x  = (const float*)d_in[0];
    const float* W1 = (const float*)d_in[1];
    const float* b1 = (const float*)d_in[2];
    const float* W2 = (const float*)d_in[3];
    const float* b2 = (const float*)d_in[4];
    float* out = (float*)d_out;

    float* outW   = out;
    float* outI   = out + 2 * Bdim;
    float* outAux = out + 4 * Bdim;

    cudaFuncSetAttribute(gemm1_fp16, cudaFuncAttributeMaxDynamicSharedMemorySize,
                         SMEM_G1);
    cudaFuncSetAttribute(fixup_h, cudaFuncAttributeMaxDynamicSharedMemorySize,
                         16 * 1024 * (int)sizeof(float));

    reset_kernel<<<1, 32>>>();
    cvt_x<<<(int)(((size_t)Bdim * Ddim) / 8 / 256), 256>>>(x);
    transpose_W1h<<<dim3(HIDd / 32, Ddim / 32), 256>>>(W1);
    gemm1_fp16<<<dim3(HIDd / 128, Bdim / 128), 256, SMEM_G1>>>(b1);
    router_kernel<<<Bdim / 32, 256>>>(W2, b2, outW, outI);
    fixup_h<<<dim3(FIXCAP / 16, 16), 128, 16 * 1024 * sizeof(float)>>>(x, W1, b1);
    fixup_logits<<<FIXCAP, 256>>>(W2, b2, outW, outI);
    aux_final<<<1, 256>>>(outAux);
}

// round 7
// speedup vs baseline: 3.4488x; 1.1448x over previous
#include <cuda_runtime.h>
#include <cuda_fp16.h>
#include <cstdint>
#include <math.h>

// ---------------------------------------------------------------------------
// ExpertRouter: h = silu(x@W1+b1); logits = h@W2+b2; top-2 softmax + aux loss.
// B=16384, D=4096, HID=2048, E=64.
// GEMM1: fp16 mma.sync m16n8k16, cp.async 4-stage, ldmatrix, 512 thr/CTA.
// Rows with top-2/3 gap < TAU recomputed exactly in fp32 (indices exact).
// Output layout (f32): [weights B*2 | top_idx(as float) B*2 | aux].
// ---------------------------------------------------------------------------

#define Bdim 16384
#define Ddim 4096
#define HIDd 2048
#define Ed   64
#define TAU  3e-3f
#define FIXCAP 4096

__device__ float  g_H[(size_t)Bdim * HIDd];     // 134 MB intermediate h (fp32)
__device__ __half g_xh[(size_t)Bdim * Ddim];    // 134 MB x in fp16
__device__ __half g_W1h[(size_t)HIDd * Ddim];   // 16.8 MB W1^T in fp16
__device__ float  g_pprob[512 * Ed];
__device__ int    g_top1[Bdim];
__device__ int    g_fixcount;
__device__ int    g_fixlist[FIXCAP];

// ---- helpers ----
__device__ __forceinline__ float silu_f(float v) { return v / (1.0f + expf(-v)); }

__device__ __forceinline__ uint32_t smem_u32(const void* p) {
    uint32_t a;
    asm("{ .reg .u64 t; cvta.to.shared.u64 t, %1; cvt.u32.u64 %0, t; }" : "=r"(a) : "l"(p));
    return a;
}
__device__ __forceinline__ void cp_async16(uint32_t saddr, const void* gaddr) {
    asm volatile("cp.async.cg.shared.global [%0], [%1], 16;" :: "r"(saddr), "l"(gaddr));
}
__device__ __forceinline__ void cp_commit() {
    asm volatile("cp.async.commit_group;");
}
template <int N>
__device__ __forceinline__ void cp_wait() {
    asm volatile("cp.async.wait_group %0;" :: "n"(N));
}
__device__ __forceinline__ void ldsm_x4(uint32_t r[4], uint32_t saddr) {
    asm volatile("ldmatrix.sync.aligned.m8n8.x4.shared.b16 {%0,%1,%2,%3}, [%4];"
                 : "=r"(r[0]), "=r"(r[1]), "=r"(r[2]), "=r"(r[3]) : "r"(saddr));
}
__device__ __forceinline__ void mma_fp16(float c[4], const uint32_t a[4],
                                         uint32_t b0, uint32_t b1) {
    asm("mma.sync.aligned.m16n8k16.row.col.f32.f16.f16.f32 "
        "{%0,%1,%2,%3}, {%4,%5,%6,%7}, {%8,%9}, {%0,%1,%2,%3};"
        : "+f"(c[0]), "+f"(c[1]), "+f"(c[2]), "+f"(c[3])
        : "r"(a[0]), "r"(a[1]), "r"(a[2]), "r"(a[3]), "r"(b0), "r"(b1));
}

// ---- packed f32x2 ----
__device__ __forceinline__ unsigned long long pack2(float lo, float hi) {
    unsigned long long r;
    asm("mov.b64 %0, {%1, %2};" : "=l"(r) : "f"(lo), "f"(hi));
    return r;
}
__device__ __forceinline__ unsigned long long fma2(unsigned long long a,
                                                   unsigned long long b,
                                                   unsigned long long c) {
    unsigned long long d;
    asm("fma.rn.f32x2 %0, %1, %2, %3;" : "=l"(d) : "l"(a), "l"(b), "l"(c));
    return d;
}
__device__ __forceinline__ float2 unpack2(unsigned long long v) {
    float2 f;
    asm("mov.b64 {%0, %1}, %2;" : "=f"(f.x), "=f"(f.y) : "l"(v));
    return f;
}

// ---------------------------------------------------------------------------
__global__ void reset_kernel() { if (threadIdx.x == 0) g_fixcount = 0; }

// ---------------------------------------------------------------------------
__global__ __launch_bounds__(256)
void cvt_x(const float* __restrict__ x) {
    size_t i = ((size_t)blockIdx.x * 256 + threadIdx.x) * 8;
    float4 f0 = *(const float4*)(x + i);
    float4 f1 = *(const float4*)(x + i + 4);
    __half2 h0 = __floats2half2_rn(f0.x, f0.y);
    __half2 h1 = __floats2half2_rn(f0.z, f0.w);
    __half2 h2 = __floats2half2_rn(f1.x, f1.y);
    __half2 h3 = __floats2half2_rn(f1.z, f1.w);
    uint4 o;
    o.x = *(uint32_t*)&h0; o.y = *(uint32_t*)&h1;
    o.z = *(uint32_t*)&h2; o.w = *(uint32_t*)&h3;
    *(uint4*)(g_xh + i) = o;
}

// ---------------------------------------------------------------------------
__global__ __launch_bounds__(256)
void transpose_W1h(const float* __restrict__ W1) {
    __shared__ float s[32][33];
    const int n0 = blockIdx.x * 32;
    const int k0 = blockIdx.y * 32;
    const int tx = threadIdx.x & 31;
    const int ty = (threadIdx.x >> 5) * 4;
#pragma unroll
    for (int i = 0; i < 4; i++)
        s[ty + i][tx] = W1[(size_t)(k0 + ty + i) * HIDd + n0 + tx];
    __syncthreads();
#pragma unroll
    for (int i = 0; i < 4; i++)
        g_W1h[(size_t)(n0 + ty + i) * Ddim + k0 + tx] = __float2half_rn(s[tx][ty + i]);
}

// ---------------------------------------------------------------------------
// GEMM1: H = silu(x @ W1 + b1). 512 thr, warps 4(m) x 4(n), warp tile 32x32.
// CTA 128x128, BK=64, cp.async 4-stage, ldmatrix.
// ---------------------------------------------------------------------------
#define BKh 64
#define LDAh 72                        // halves per row (144 B)
#define ARRH (128 * LDAh)
#define STG_H (2 * ARRH)
#define NSTAGE 4
#define SMEM_G1 (NSTAGE * STG_H * 2)   // 147456 bytes

__global__ __launch_bounds__(512, 1)
void gemm1_fp16(const float* __restrict__ b1) {
    extern __shared__ __half smh[];
    const uint32_t sbase = smem_u32(smh);

    const int tid = threadIdx.x;
    const int wid = tid >> 5, lane = tid & 31;
    const int rowBase = blockIdx.y * 128, colBase = blockIdx.x * 128;
    const int wm = (wid & 3) * 32, wn = (wid >> 2) * 32;

    const __half* Ag = g_xh  + (size_t)rowBase * Ddim;
    const __half* Bg = g_W1h + (size_t)colBase * Ddim;

    // cp.async mapping: 2048 16B-chunks per stage, 4 per thread
    int ld_arr[4], ld_row[4], ld_off[4];
    uint32_t ld_saddr[4];
#pragma unroll
    for (int i = 0; i < 4; i++) {
        int c = tid + 512 * i;
        ld_arr[i] = c >> 10;
        int rem = c & 1023;
        ld_row[i] = rem >> 3;
        ld_off[i] = (rem & 7) * 8;
        ld_saddr[i] = sbase + (uint32_t)(ld_arr[i] * ARRH + ld_row[i] * LDAh + ld_off[i]) * 2;
    }

    // ldmatrix lane addresses (byte offsets within stage)
    const int a_m = wm + (lane & 15);
    const int a_k = ((lane >> 4) & 1) * 8;
    const uint32_t aOff0 = (uint32_t)(a_m * LDAh + a_k) * 2;
    const uint32_t aOff1 = (uint32_t)((a_m + 16) * LDAh + a_k) * 2;
    const int b_k = ((lane >> 3) & 1) * 8;
    uint32_t bOff[2];
#pragma unroll
    for (int p = 0; p < 2; p++) {
        int n = wn + p * 16 + (lane & 7) + ((lane >> 4) & 1) * 8;
        bOff[p] = (uint32_t)(ARRH + n * LDAh + b_k) * 2;
    }

    float acc[2][4][4];
#pragma unroll
    for (int mt = 0; mt < 2; mt++)
#pragma unroll
        for (int nt = 0; nt < 4; nt++)
#pragma unroll
            for (int r = 0; r < 4; r++) acc[mt][nt][r] = 0.0f;

    const int NCHUNK = Ddim / BKh;   // 64

#pragma unroll
    for (int kc = 0; kc < NSTAGE - 1; kc++) {
        const int k0 = kc * BKh;
        const uint32_t sb = (uint32_t)(kc & 3) * STG_H * 2;
#pragma unroll
        for (int i = 0; i < 4; i++) {
            const __half* g = (ld_arr[i] ? Bg : Ag) +
                              (size_t)ld_row[i] * Ddim + k0 + ld_off[i];
            cp_async16(ld_saddr[i] + sb, g);
        }
        cp_commit();
    }

    for (int kc = 0; kc < NCHUNK; kc++) {
        cp_wait<NSTAGE - 2>();
        __syncthreads();

        if (kc + NSTAGE - 1 < NCHUNK) {
            const int k0 = (kc + NSTAGE - 1) * BKh;
            const uint32_t sb = (uint32_t)((kc + NSTAGE - 1) & 3) * STG_H * 2;
#pragma unroll
            for (int i = 0; i < 4; i++) {
                const __half* g = (ld_arr[i] ? Bg : Ag) +
                                  (size_t)ld_row[i] * Ddim + k0 + ld_off[i];
                cp_async16(ld_saddr[i] + sb, g);
            }
            cp_commit();
        }

        const uint32_t sb = sbase + (uint32_t)(kc & 3) * STG_H * 2;
#pragma unroll
        for (int st = 0; st < 4; st++) {
            const uint32_t kb = (uint32_t)(st * 16) * 2;
            uint32_t a0[4], a1[4];
            ldsm_x4(a0, sb + aOff0 + kb);
            ldsm_x4(a1, sb + aOff1 + kb);
#pragma unroll
            for (int p = 0; p < 2; p++) {
                uint32_t bfr[4];
                ldsm_x4(bfr, sb + bOff[p] + kb);
                mma_fp16(acc[0][2 * p],     a0, bfr[0], bfr[1]);
                mma_fp16(acc[1][2 * p],     a1, bfr[0], bfr[1]);
                mma_fp16(acc[0][2 * p + 1], a0, bfr[2], bfr[3]);
                mma_fp16(acc[1][2 * p + 1], a1, bfr[2], bfr[3]);
            }
        }
        __syncthreads();
    }

    // epilogue: bias + silu -> g_H
    const int g = lane >> 2, t = lane & 3;
#pragma unroll
    for (int nt = 0; nt < 4; nt++) {
        const int n0 = colBase + wn + nt * 8 + t * 2;
        const float bs0 = b1[n0];
        const float bs1 = b1[n0 + 1];
#pragma unroll
        for (int mt = 0; mt < 2; mt++) {
            const int m0 = rowBase + wm + mt * 16 + g;
            float2 o0, o1;
            o0.x = silu_f(acc[mt][nt][0] + bs0);
            o0.y = silu_f(acc[mt][nt][1] + bs1);
            o1.x = silu_f(acc[mt][nt][2] + bs0);
            o1.y = silu_f(acc[mt][nt][3] + bs1);
            *(float2*)(g_H + (size_t)m0 * HIDd + n0)       = o0;
            *(float2*)(g_H + (size_t)(m0 + 8) * HIDd + n0) = o1;
        }
    }
}

// ---------------------------------------------------------------------------
// Router: logits = H @ W2 + b2; top-2 / softmax / prob partials / tie flags.
// ---------------------------------------------------------------------------
__global__ __launch_bounds__(256)
void router_kernel(const float* __restrict__ W2,
                   const float* __restrict__ b2,
                   float* __restrict__ outW,
                   float* __restrict__ outI) {
    __shared__ float sW2[128][Ed];
    __shared__ float sH[32][128];
    __shared__ float sProb[32][Ed];

    const int tid  = threadIdx.x;
    const int warp = tid >> 5;
    const int lane = tid & 31;
    const int rowBase = blockIdx.x * 32;

    unsigned long long acc[4] = {0ULL, 0ULL, 0ULL, 0ULL};

    for (int kc = 0; kc < HIDd; kc += 128) {
        __syncthreads();
#pragma unroll
        for (int i = 0; i < 8; i++) {
            int idx = tid + 256 * i;
            int r = idx >> 4, c4 = (idx & 15) * 4;
            *(float4*)&sW2[r][c4] = *(const float4*)&W2[(size_t)(kc + r) * Ed + c4];
        }
#pragma unroll
        for (int i = 0; i < 4; i++) {
            int idx = tid + 256 * i;
            int r = idx >> 5, c = (idx & 31) * 4;
            *(float4*)&sH[r][c] = *(const float4*)&g_H[(size_t)(rowBase + r) * HIDd + kc + c];
        }
        __syncthreads();

#pragma unroll 2
        for (int k4 = 0; k4 < 32; k4++) {
            unsigned long long wv0 = *(const unsigned long long*)&sW2[k4 * 4 + 0][lane * 2];
            unsigned long long wv1 = *(const unsigned long long*)&sW2[k4 * 4 + 1][lane * 2];
            unsigned long long wv2 = *(const unsigned long long*)&sW2[k4 * 4 + 2][lane * 2];
            unsigned long long wv3 = *(const unsigned long long*)&sW2[k4 * 4 + 3][lane * 2];
#pragma unroll
            for (int r = 0; r < 4; r++) {
                float4 h4 = *(const float4*)&sH[warp * 4 + r][k4 * 4];
                acc[r] = fma2(pack2(h4.x, h4.x), wv0, acc[r]);
                acc[r] = fma2(pack2(h4.y, h4.y), wv1, acc[r]);
                acc[r] = fma2(pack2(h4.z, h4.z), wv2, acc[r]);
                acc[r] = fma2(pack2(h4.w, h4.w), wv3, acc[r]);
            }
        }
    }

    const float b2a = b2[lane * 2];
    const float b2b = b2[lane * 2 + 1];

#pragma unroll
    for (int r = 0; r < 4; r++) {
        const int lrow = warp * 4 + r;
        float2 av = unpack2(acc[r]);
        float l0 = av.x + b2a;
        float l1 = av.y + b2b;
        const int id0 = lane * 2, id1 = lane * 2 + 1;

        float bvv, sv; int bi, si;
        if (l0 >= l1) { bvv = l0; bi = id0; sv = l1; si = id1; }
        else          { bvv = l1; bi = id1; sv = l0; si = id0; }

        float v1 = bvv; int i1 = bi;
#pragma unroll
        for (int off = 16; off; off >>= 1) {
            float ov = __shfl_down_sync(0xffffffffu, v1, off);
            int   oi = __shfl_down_sync(0xffffffffu, i1, off);
            if (ov > v1 || (ov == v1 && oi < i1)) { v1 = ov; i1 = oi; }
        }
        v1 = __shfl_sync(0xffffffffu, v1, 0);
        i1 = __shfl_sync(0xffffffffu, i1, 0);

        float cv; int ci;
        if (bi == i1) { cv = sv; ci = si; } else { cv = bvv; ci = bi; }
        float v2 = cv; int i2 = ci;
#pragma unroll
        for (int off = 16; off; off >>= 1) {
            float ov = __shfl_down_sync(0xffffffffu, v2, off);
            int   oi = __shfl_down_sync(0xffffffffu, i2, off);
            if (ov > v2 || (ov == v2 && oi < i2)) { v2 = ov; i2 = oi; }
        }
        v2 = __shfl_sync(0xffffffffu, v2, 0);
        i2 = __shfl_sync(0xffffffffu, i2, 0);

        float v3 = -1e30f;
        if (id0 != i1 && id0 != i2) v3 = l0;
        if (id1 != i1 && id1 != i2 && l1 > v3) v3 = l1;
#pragma unroll
        for (int off = 16; off; off >>= 1) {
            float ov = __shfl_down_sync(0xffffffffu, v3, off);
            if (ov > v3) v3 = ov;
        }

        float p0 = expf(l0 - v1);
        float p1 = expf(l1 - v1);
        float ssum = p0 + p1;
#pragma unroll
        for (int off = 16; off; off >>= 1) ssum += __shfl_down_sync(0xffffffffu, ssum, off);
        ssum = __shfl_sync(0xffffffffu, ssum, 0);
        float inv = 1.0f / ssum;
        sProb[lrow][lane * 2]     = p0 * inv;
        sProb[lrow][lane * 2 + 1] = p1 * inv;

        if (lane == 0) {
            float d = expf(v2 - v1);
            float w0 = 1.0f / (1.0f + d);
            float w1 = d / (1.0f + d);
            size_t gb = (size_t)(rowBase + lrow);
            outW[gb * 2]     = w0;
            outW[gb * 2 + 1] = w1;
            outI[gb * 2]     = (float)i1;
            outI[gb * 2 + 1] = (float)i2;
            g_top1[gb]       = i1;
            if ((v1 - v2) < TAU || (v2 - v3) < TAU) {
                int pos = atomicAdd(&g_fixcount, 1);
                if (pos < FIXCAP) g_fixlist[pos] = (int)gb;
            }
        }
    }
    __syncthreads();

    if (tid < Ed) {
        float ps = 0.0f;
#pragma unroll
        for (int r = 0; r < 32; r++) ps += sProb[r][tid];
        g_pprob[(size_t)blockIdx.x * Ed + tid] = ps;
    }
}

// ---------------------------------------------------------------------------
// Fixup stage 1 (v2): exact fp32 h for flagged rows.
// 16 rows/group; 128 thr, 4 cols/thread => 512 cols/block, 4 col-slices.
// smem: pre-packed row-pair f32x2: 1024 k x 8 pairs x 8B = 64 KB.
// ---------------------------------------------------------------------------
__global__ __launch_bounds__(128)
void fixup_h(const float* __restrict__ x,
             const float* __restrict__ W1,
             const float* __restrict__ b1) {
    extern __shared__ unsigned long long sXP[];   // [1024][8]
    int cnt = g_fixcount; if (cnt > FIXCAP) cnt = FIXCAP;
    if (blockIdx.x * 16 >= cnt) return;
    const int tid = threadIdx.x;
    const int col = blockIdx.y * 512 + tid * 4;

    int rows[16];
#pragma unroll
    for (int r = 0; r < 16; r++) {
        int gi = blockIdx.x * 16 + r;
        rows[r] = g_fixlist[gi < cnt ? gi : cnt - 1];
    }

    unsigned long long acc2[8][4];
#pragma unroll
    for (int p = 0; p < 8; p++)
#pragma unroll
        for (int c = 0; c < 4; c++) acc2[p][c] = 0ULL;

    for (int q = 0; q < 4; q++) {
        __syncthreads();
        // pack pairs: idx -> p = idx>>10 (0..7), k = idx&1023
        for (int idx = tid; idx < 8 * 1024; idx += 128) {
            int p = idx >> 10, kk = idx & 1023;
            float xa = x[(size_t)rows[2 * p]     * Ddim + q * 1024 + kk];
            float xb = x[(size_t)rows[2 * p + 1] * Ddim + q * 1024 + kk];
            sXP[(size_t)kk * 8 + p] = pack2(xa, xb);
        }
        __syncthreads();
        for (int kk = 0; kk < 1024; kk++) {
            float4 w = *(const float4*)&W1[(size_t)(q * 1024 + kk) * HIDd + col];
            unsigned long long wq[4];
            wq[0] = pack2(w.x, w.x); wq[1] = pack2(w.y, w.y);
            wq[2] = pack2(w.z, w.z); wq[3] = pack2(w.w, w.w);
            const unsigned long long* xp = &sXP[(size_t)kk * 8];
#pragma unroll
            for (int p = 0; p < 8; p++) {
                unsigned long long xv = xp[p];
                acc2[p][0] = fma2(xv, wq[0], acc2[p][0]);
                acc2[p][1] = fma2(xv, wq[1], acc2[p][1]);
                acc2[p][2] = fma2(xv, wq[2], acc2[p][2]);
                acc2[p][3] = fma2(xv, wq[3], acc2[p][3]);
            }
        }
    }

    float4 bb = *(const float4*)&b1[col];
    const float* bbp = (const float*)&bb;
#pragma unroll
    for (int p = 0; p < 8; p++) {
        int gi0 = blockIdx.x * 16 + 2 * p;
        int gi1 = gi0 + 1;
#pragma unroll
        for (int c = 0; c < 4; c++) {
            float2 v = unpack2(acc2[p][c]);
            if (gi0 < cnt) g_H[(size_t)rows[2 * p]     * HIDd + col + c] = silu_f(v.x + bbp[c]);
            if (gi1 < cnt) g_H[(size_t)rows[2 * p + 1] * HIDd + col + c] = silu_f(v.y + bbp[c]);
        }
    }
}

// ---------------------------------------------------------------------------
// Fixup stage 2: exact logits + top2 + weights for flagged rows.
// ---------------------------------------------------------------------------
__global__ __launch_bounds__(256)
void fixup_logits(const float* __restrict__ W2,
                  const float* __restrict__ b2,
                  float* __restrict__ outW,
                  float* __restrict__ outI) {
    int cnt = g_fixcount; if (cnt > FIXCAP) cnt = FIXCAP;
    const int fi = blockIdx.x;
    if (fi >= cnt) return;
    const int row = g_fixlist[fi];
    const int tid = threadIdx.x;
    const int e = tid & 63, q = tid >> 6;
    __shared__ float part[4][Ed];
    __shared__ float sLog[Ed];

    float a = 0.0f;
    const float* hrow = g_H + (size_t)row * HIDd;
    for (int k = q * 512; k < (q + 1) * 512; k++)
        a = fmaf(hrow[k], W2[(size_t)k * Ed + e], a);
    part[q][e] = a;
    __syncthreads();
    if (tid < Ed)
        sLog[tid] = part[0][tid] + part[1][tid] + part[2][tid] + part[3][tid] + b2[tid];
    __syncthreads();
    if (tid == 0) {
        float v1 = -1e30f, v2 = -1e30f; int i1 = 0, i2 = 0;
        for (int j = 0; j < Ed; j++) {
            float v = sLog[j];
            if (v > v1)      { v2 = v1; i2 = i1; v1 = v; i1 = j; }
            else if (v > v2) { v2 = v;  i2 = j; }
        }
        float d = expf(v2 - v1);
        outW[(size_t)row * 2]     = 1.0f / (1.0f + d);
        outW[(size_t)row * 2 + 1] = d / (1.0f + d);
        outI[(size_t)row * 2]     = (float)i1;
        outI[(size_t)row * 2 + 1] = (float)i2;
        g_top1[row] = i1;
    }
}

// ---------------------------------------------------------------------------
__global__ __launch_bounds__(256)
void aux_final(float* __restrict__ outAux) {
    __shared__ int   hist[Ed];
    __shared__ float term[Ed];
    const int tid = threadIdx.x;
    if (tid < Ed) hist[tid] = 0;
    __syncthreads();
    for (int r = tid; r < Bdim; r += 256)
        atomicAdd(&hist[g_top1[r]], 1);
    __syncthreads();
    if (tid < Ed) {
        float p = 0.0f;
        for (int b = 0; b < 512; b++) p += g_pprob[b * Ed + tid];
        term[tid] = ((float)hist[tid] * (1.0f / (float)Bdim)) *
                    (p * (1.0f / (float)Bdim));
    }
    __syncthreads();
    if (tid == 0) {
        float s = 0.0f;
        for (int e = 0; e < Ed; e++) s += term[e];
        outAux[0] = (float)Ed * s;
    }
}

// ---------------------------------------------------------------------------
extern "C" void kernel_launch(void* const* d_in, const int* in_sizes, int n_in,
                              void* d_out, int out_size) {
    const float* x  = (const float*)d_in[0];
    const float* W1 = (const float*)d_in[1];
    const float* b1 = (const float*)d_in[2];
    const float* W2 = (const float*)d_in[3];
    const float* b2 = (const float*)d_in[4];
    float* out = (float*)d_out;

    float* outW   = out;
    float* outI   = out + 2 * Bdim;
    float* outAux = out + 4 * Bdim;

    cudaFuncSetAttribute(gemm1_fp16, cudaFuncAttributeMaxDynamicSharedMemorySize,
                         SMEM_G1);
    cudaFuncSetAttribute(fixup_h, cudaFuncAttributeMaxDynamicSharedMemorySize,
                         8 * 1024 * 8);

    reset_kernel<<<1, 32>>>();
    cvt_x<<<(int)(((size_t)Bdim * Ddim) / 8 / 256), 256>>>(x);
    transpose_W1h<<<dim3(HIDd / 32, Ddim / 32), 256>>>(W1);
    gemm1_fp16<<<dim3(HIDd / 128, Bdim / 128), 512, SMEM_G1>>>(b1);
    router_kernel<<<Bdim / 32, 256>>>(W2, b2, outW, outI);
    fixup_h<<<dim3(FIXCAP / 16, 4), 128, 8 * 1024 * 8>>>(x, W1, b1);
    fixup_logits<<<FIXCAP, 256>>>(W2, b2, outW, outI);
    aux_final<<<1, 256>>>(outAux);
}